// round 1
// baseline (speedup 1.0000x reference)
#include <cuda_runtime.h>

// Problem dims
// N=32, T=64, D=16, F=512; graphs = N*T = 2048

// Scratch (allocation-free: __device__ globals)
__device__ float g_obj[2048 * 16 * 512];   // 64 MB
__device__ float g_feat[2048 * 512];       // 4 MB
__device__ float g_c[2048 * 1024];         // 8 MB
__device__ float g_cbar[32 * 1024];        // 128 KB

// ---------------------------------------------------------------------------
// Tiled fp32 GEMM: C[row*ldc + coff + col] = (RELU?) (A@B + bias)
// A: [M,K] row-major, B: [K,N] row-major. Requires M%128==0, N%128==0, K%8==0.
// BM=BN=128, BK=8, 8x8 micro-tile, 256 threads.
// ---------------------------------------------------------------------------
template <bool RELU>
__global__ __launch_bounds__(256) void gemm_bias(
    const float* __restrict__ A, const float* __restrict__ B,
    const float* __restrict__ bias, float* __restrict__ C,
    int M, int N, int K, int ldc, int coff)
{
    __shared__ float As[8][132];   // padded: conflict-free transposed stores
    __shared__ float Bs[8][128];

    const int t  = threadIdx.x;
    const int bm = blockIdx.y * 128;
    const int bn = blockIdx.x * 128;
    const int tm = (t >> 4) * 8;
    const int tn = (t & 15) * 8;

    const int arow = t >> 1, akc = (t & 1) * 4;   // A: row, k-offset (float4)
    const int bkr  = t >> 5, bnc = (t & 31) * 4;  // B: k-row, n-offset (float4)

    const float* Aptr = A + (size_t)(bm + arow) * K + akc;
    const float* Bptr = B + (size_t)bkr * N + bn + bnc;

    float acc[8][8];
#pragma unroll
    for (int i = 0; i < 8; i++)
#pragma unroll
        for (int j = 0; j < 8; j++) acc[i][j] = 0.f;

    for (int k0 = 0; k0 < K; k0 += 8) {
        float4 av = *(const float4*)(Aptr + k0);
        As[akc + 0][arow] = av.x;
        As[akc + 1][arow] = av.y;
        As[akc + 2][arow] = av.z;
        As[akc + 3][arow] = av.w;
        *(float4*)(&Bs[bkr][bnc]) = *(const float4*)(Bptr + (size_t)k0 * N);
        __syncthreads();

#pragma unroll
        for (int kk = 0; kk < 8; kk++) {
            float a[8], b[8];
            *(float4*)(a)     = *(const float4*)(&As[kk][tm]);
            *(float4*)(a + 4) = *(const float4*)(&As[kk][tm + 4]);
            *(float4*)(b)     = *(const float4*)(&Bs[kk][tn]);
            *(float4*)(b + 4) = *(const float4*)(&Bs[kk][tn + 4]);
#pragma unroll
            for (int i = 0; i < 8; i++)
#pragma unroll
                for (int j = 0; j < 8; j++) acc[i][j] += a[i] * b[j];
        }
        __syncthreads();
    }

#pragma unroll
    for (int i = 0; i < 8; i++) {
        int row = bm + tm + i;
#pragma unroll
        for (int j = 0; j < 8; j += 4) {
            int col = bn + tn + j;
            float4 bv = *(const float4*)(bias + col);
            float4 o;
            o.x = acc[i][j + 0] + bv.x;
            o.y = acc[i][j + 1] + bv.y;
            o.z = acc[i][j + 2] + bv.z;
            o.w = acc[i][j + 3] + bv.w;
            if (RELU) {
                o.x = fmaxf(o.x, 0.f); o.y = fmaxf(o.y, 0.f);
                o.z = fmaxf(o.z, 0.f); o.w = fmaxf(o.w, 0.f);
            }
            *(float4*)(C + (size_t)row * ldc + coff + col) = o;
        }
    }
}

// ---------------------------------------------------------------------------
// Per-graph GCN kernel: one block (256 thr) per graph of x = obj[g] : [16,512].
// Produces feat[g][:] = relu( (mean_D(obj) + 0.5*(mean_D x1 + mean_D y2)) * 0.5 )
// using the linearity trick: mean_i (adj @ t)[i][c] = sum_j (mean_i adj[i][j]) t[j][c].
// ---------------------------------------------------------------------------
#define XS 516   // padded x stride (reduces smem bank conflicts in x@x^T)

__global__ __launch_bounds__(256) void graph_kernel(
    const float* __restrict__ obj,
    const float* __restrict__ gc1_W, const float* __restrict__ gc1_b,
    const float* __restrict__ gc2_W, const float* __restrict__ gc2_b,
    const float* __restrict__ gc3_W, const float* __restrict__ gc3_b,
    const float* __restrict__ gc4_W, const float* __restrict__ gc4_b,
    float* __restrict__ feat)
{
    __shared__ float sx[16 * XS];     // x tile [16,512] (33 KB)
    __shared__ float s_adj[16][17];   // s, then exp, then normalized adj
    __shared__ float s_a3[16][17];    // y22, then adj3, then adj_hat3
    __shared__ float s_w1[16][33];    // x @ gc1_W
    __shared__ float s_w3[16][33];    // x @ gc3_W
    __shared__ float s_h1[16][33];    // relu(adj@xw1 + b1)
    __shared__ float s_y2[16][33];    // relu(adj@xw3 + b3)
    __shared__ float s_d[16], s_m1[16], s_m3[16];
    __shared__ float s_hbar[32], s_ybar[32];

    const int g = blockIdx.x;
    const int t = threadIdx.x;
    const float* x = obj + (size_t)g * 16 * 512;

    // load x -> smem (float4)
    for (int idx = t * 4; idx < 16 * 512; idx += 256 * 4) {
        int i = idx >> 9, k = idx & 511;
        *(float4*)(sx + i * XS + k) = *(const float4*)(x + idx);
    }
    __syncthreads();

    // omean (mean over D of obj) in registers: this thread owns cols t, t+256
    const int c0 = t, c1 = t + 256;
    float om0 = 0.f, om1 = 0.f;
#pragma unroll
    for (int i = 0; i < 16; i++) { om0 += sx[i * XS + c0]; om1 += sx[i * XS + c1]; }
    om0 *= (1.f / 16.f); om1 *= (1.f / 16.f);

    // s = x @ x^T  (thread (i,j) -> 512-dot)
    {
        const int i = t >> 4, j = t & 15;
        float acc = 0.f;
        for (int k = 0; k < 512; k++) acc += sx[i * XS + k] * sx[j * XS + k];
        s_adj[i][j] = acc;
    }
    // xw1 = x@gc1_W, xw3 = x@gc3_W  ([16,32], 2 rows/thread), fused over shared x
    {
        const int j = t & 31, i0 = t >> 5;
        float a1a = 0, a1b = 0, a3a = 0, a3b = 0;
        for (int k = 0; k < 512; k++) {
            float w1 = gc1_W[k * 32 + j], w3 = gc3_W[k * 32 + j];
            float xa = sx[i0 * XS + k], xb = sx[(i0 + 8) * XS + k];
            a1a += xa * w1; a3a += xa * w3;
            a1b += xb * w1; a3b += xb * w3;
        }
        s_w1[i0][j] = a1a; s_w1[i0 + 8][j] = a1b;
        s_w3[i0][j] = a3a; s_w3[i0 + 8][j] = a3b;
    }
    __syncthreads();

    // adjacency: row softmax-exp + D^{-1/2}
    if (t < 16) {
        float mx = -1e30f;
#pragma unroll
        for (int j = 0; j < 16; j++) mx = fmaxf(mx, s_adj[t][j]);
        float sum = 0.f;
#pragma unroll
        for (int j = 0; j < 16; j++) { float e = expf(s_adj[t][j] - mx); s_adj[t][j] = e; sum += e; }
        s_d[t] = rsqrtf(sum);
    }
    __syncthreads();
    {
        const int i = t >> 4, j = t & 15;
        s_adj[i][j] = s_adj[i][j] * s_d[i] * s_d[j];
    }
    __syncthreads();

    // m1[j] = mean_i adj[i][j] ; and h1/y2 = relu(adj @ xw + b) (adj read-only here)
    if (t < 16) {
        float s = 0.f;
#pragma unroll
        for (int i = 0; i < 16; i++) s += s_adj[i][t];
        s_m1[t] = s * (1.f / 16.f);
    }
    {
        const int j = t & 31, i0 = t >> 5;
#pragma unroll
        for (int rep = 0; rep < 2; rep++) {
            const int i = i0 + rep * 8;
            float a1 = gc1_b[j], a3 = gc3_b[j];
#pragma unroll
            for (int l = 0; l < 16; l++) {
                float ad = s_adj[i][l];
                a1 += ad * s_w1[l][j];
                a3 += ad * s_w3[l][j];
            }
            s_h1[i][j] = fmaxf(a1, 0.f);
            s_y2[i][j] = fmaxf(a3, 0.f);
        }
    }
    __syncthreads();

    // y22 = y2 @ y2^T
    {
        const int i = t >> 4, j = t & 15;
        float acc = 0.f;
#pragma unroll
        for (int l = 0; l < 32; l++) acc += s_y2[i][l] * s_y2[j][l];
        s_a3[i][j] = acc;
    }
    __syncthreads();
    // nrm[i] = ||y22_row_i||_2
    if (t < 16) {
        float ss = 0.f;
#pragma unroll
        for (int j = 0; j < 16; j++) { float v = s_a3[t][j]; ss += v * v; }
        s_d[t] = sqrtf(ss);
    }
    __syncthreads();
    // adj3 = 1 + y22/(nrm_i*nrm_j)
    {
        const int i = t >> 4, j = t & 15;
        s_a3[i][j] = 1.f + s_a3[i][j] / (s_d[i] * s_d[j]);
    }
    __syncthreads();
    // D^{-1/2} normalize adj3
    if (t < 16) {
        float sum = 0.f;
#pragma unroll
        for (int j = 0; j < 16; j++) sum += s_a3[t][j];
        s_d[t] = rsqrtf(sum);
    }
    __syncthreads();
    {
        const int i = t >> 4, j = t & 15;
        s_a3[i][j] = s_a3[i][j] * s_d[i] * s_d[j];
    }
    __syncthreads();
    // m3[j] = mean_i adj_hat3[i][j]
    if (t < 16) {
        float s = 0.f;
#pragma unroll
        for (int i = 0; i < 16; i++) s += s_a3[i][t];
        s_m3[t] = s * (1.f / 16.f);
    }
    __syncthreads();

    // hbar[l] = sum_j m1[j]*h1[j][l];  ybar[l] = sum_j m3[j]*y2[j][l]
    if (t < 32) {
        float s = 0.f;
#pragma unroll
        for (int j = 0; j < 16; j++) s += s_m1[j] * s_h1[j][t];
        s_hbar[t] = s;
    } else if (t < 64) {
        const int l = t - 32;
        float s = 0.f;
#pragma unroll
        for (int j = 0; j < 16; j++) s += s_m3[j] * s_y2[j][l];
        s_ybar[l] = s;
    }
    __syncthreads();

    // gsum[c] = (hbar @ gc2_W)[c] + gc2_b[c] + (ybar @ gc4_W)[c] + gc4_b[c]
    float gm0 = gc2_b[c0] + gc4_b[c0];
    float gm1 = gc2_b[c1] + gc4_b[c1];
#pragma unroll
    for (int l = 0; l < 32; l++) {
        float hb = s_hbar[l], yb = s_ybar[l];
        gm0 += hb * gc2_W[l * 512 + c0] + yb * gc4_W[l * 512 + c0];
        gm1 += hb * gc2_W[l * 512 + c1] + yb * gc4_W[l * 512 + c1];
    }

    // feat = relu((omean + 0.5*gsum)*0.5)
    feat[(size_t)g * 512 + c0] = fmaxf((om0 + 0.5f * gm0) * 0.5f, 0.f);
    feat[(size_t)g * 512 + c1] = fmaxf((om1 + 0.5f * gm1) * 0.5f, 0.f);
}

// ---------------------------------------------------------------------------
// cbar[n][k] = mean_t c[(n*64+t)][k]   (mean over T before clf: linearity)
// ---------------------------------------------------------------------------
__global__ void reduce_T(const float* __restrict__ c, float* __restrict__ cbar)
{
    const int n = blockIdx.y;
    const int k = blockIdx.x * 256 + threadIdx.x;   // 0..1023
    float s = 0.f;
#pragma unroll 8
    for (int tt = 0; tt < 64; tt++)
        s += c[(size_t)(n * 64 + tt) * 1024 + k];
    cbar[n * 1024 + k] = s * (1.f / 64.f);
}

// ---------------------------------------------------------------------------
// out[n][j] = cbar[n] @ clf_W[:,j] + clf_b[j]   (32 x 500, K=1024)
// ---------------------------------------------------------------------------
__global__ __launch_bounds__(512) void clf_kernel(
    const float* __restrict__ cbar, const float* __restrict__ W,
    const float* __restrict__ b, float* __restrict__ out)
{
    __shared__ float sc[1024];
    const int n = blockIdx.x;
    for (int k = threadIdx.x; k < 1024; k += 512) sc[k] = cbar[n * 1024 + k];
    __syncthreads();
    const int j = threadIdx.x;
    if (j < 500) {
        float acc = b[j];
        for (int k = 0; k < 1024; k++) acc += sc[k] * W[k * 500 + j];
        out[n * 500 + j] = acc;
    }
}

// ---------------------------------------------------------------------------
extern "C" void kernel_launch(void* const* d_in, const int* in_sizes, int n_in,
                              void* d_out, int out_size)
{
    const float* object_raw = (const float*)d_in[0];
    const float* action_raw = (const float*)d_in[1];
    const float* W_obj = (const float*)d_in[2];
    const float* b_obj = (const float*)d_in[3];
    const float* W_act = (const float*)d_in[4];
    const float* b_act = (const float*)d_in[5];
    const float* gc1_W = (const float*)d_in[6];
    const float* gc1_b = (const float*)d_in[7];
    const float* gc2_W = (const float*)d_in[8];
    const float* gc2_b = (const float*)d_in[9];
    const float* gc3_W = (const float*)d_in[10];
    const float* gc3_b = (const float*)d_in[11];
    const float* gc4_W = (const float*)d_in[12];
    const float* gc4_b = (const float*)d_in[13];
    const float* fc1_W = (const float*)d_in[14];
    const float* fc1_b = (const float*)d_in[15];
    const float* clf_W = (const float*)d_in[16];
    const float* clf_b = (const float*)d_in[17];
    float* out = (float*)d_out;

    float *p_obj, *p_feat, *p_c, *p_cbar;
    cudaGetSymbolAddress((void**)&p_obj, g_obj);
    cudaGetSymbolAddress((void**)&p_feat, g_feat);
    cudaGetSymbolAddress((void**)&p_c, g_c);
    cudaGetSymbolAddress((void**)&p_cbar, g_cbar);

    // 1) obj = relu(object_raw @ W_obj + b_obj)  -> [32768,512] laid out [2048,16,512]
    gemm_bias<true><<<dim3(512 / 128, 32768 / 128), 256>>>(
        object_raw, W_obj, b_obj, p_obj, 32768, 512, 512, 512, 0);

    // 2) act = relu(action_raw @ W_act + b_act) -> overwrite middle frame (d=8)
    gemm_bias<true><<<dim3(512 / 128, 2048 / 128), 256>>>(
        action_raw, W_act, b_act, p_obj, 2048, 512, 512, 16 * 512, 8 * 512);

    // 3) per-graph GCN + D-mean fusion -> feat = relu((o + g)*0.5) : [2048,512]
    graph_kernel<<<2048, 256>>>(p_obj, gc1_W, gc1_b, gc2_W, gc2_b,
                                gc3_W, gc3_b, gc4_W, gc4_b, p_feat);

    // 4) c = relu(feat @ fc1_W + fc1_b) : [2048,1024]
    gemm_bias<true><<<dim3(1024 / 128, 2048 / 128), 256>>>(
        p_feat, fc1_W, fc1_b, p_c, 2048, 1024, 512, 1024, 0);

    // 5) mean over T -> cbar [32,1024]
    reduce_T<<<dim3(4, 32), 256>>>(p_c, p_cbar);

    // 6) out = cbar @ clf_W + clf_b : [32,500]
    clf_kernel<<<32, 512>>>(p_cbar, clf_W, clf_b, out);
}